// round 1
// baseline (speedup 1.0000x reference)
#include <cuda_runtime.h>
#include <cstdint>

#define Bn 256
#define Tn 1024
#define Cn 256
#define Ln 128
#define Sn 257          // 2L+1
#define DEPTH 12        // cp.async ring depth
#define NEGF (-1e30f)
#define EPSF (1e-7f)
#define NTHREADS 288    // 9 warps: states + helpers

// State->thread map:
//   tid 0..128   : even states s = 2*tid   (blank states, 2-term LSE)  [warps 0..4]
//   tid 160..287 : odd  states s = 2*(tid-160)+1 (label states, 3-term) [warps 5..8]
//   tid 129..159 : no state; tids 128..159 do the row-sum stage-A,
//                  tids 132..139 rotate stage-B (row-sum finalize).
//   tids 0..63   : issue cp.async row prefetches (16B each).

__global__ __launch_bounds__(NTHREADS, 2)
void ctc_kernel(const void* __restrict__ yt_raw,
                const float* __restrict__ yp,
                float* __restrict__ out)
{
    __shared__ __align__(16) float rowring[DEPTH][Cn];
    __shared__ float abuf[2][Sn + 2];      // alpha stored at [2+s]; [0],[1] = NEG sentinels
    __shared__ __align__(16) float partA[2][32];
    __shared__ float sums[Tn];
    __shared__ int   labs[Ln];
    __shared__ float wsum[8];
    __shared__ int   flag64;

    const int b   = blockIdx.x;
    const int tid = threadIdx.x;
    const float* rowbase = yp + (size_t)b * Tn * Cn;

    if (tid == 0) flag64 = 1;
    __syncthreads();

    // ---- prologue: prefetch rows 0..DEPTH-1 into the ring ----
    if (tid < 64) {
        #pragma unroll
        for (int r = 0; r < DEPTH; ++r) {
            unsigned saddr = (unsigned)__cvta_generic_to_shared(&rowring[r][tid * 4]);
            const float* g = rowbase + (size_t)r * Cn + tid * 4;
            asm volatile("cp.async.cg.shared.global [%0], [%1], 16;\n" :: "r"(saddr), "l"(g));
            asm volatile("cp.async.commit_group;\n");
        }
    }

    // ---- detect label dtype (int64 vs int32): int64 => odd int32 words are 0 ----
    {
        const int* i32 = (const int*)yt_raw;
        if (tid < 128) { if (i32[2 * tid + 1] != 0) flag64 = 0; }
    }
    if (tid < 2) { abuf[0][tid] = NEGF; abuf[1][tid] = NEGF; }
    __syncthreads();

    if (tid < Ln) {
        if (flag64) labs[tid] = (int)((const long long*)yt_raw)[(size_t)b * Ln + tid];
        else        labs[tid] = ((const int*)yt_raw)[(size_t)b * Ln + tid];
    }

    asm volatile("cp.async.wait_group %0;\n" :: "n"(DEPTH - 1));
    __syncthreads();

    // ---- per-thread state config ----
    int  s = -1, myext = Cn - 1;
    bool oddst = false, skipok = false;
    if (tid <= 128) {
        s = 2 * tid;                      // even (blank) states, incl. s=256
    } else if (tid >= 160) {
        int i = tid - 160;                // 0..127
        s = 2 * i + 1;
        oddst = true;
        myext = labs[i];
        skipok = (i > 0) && (labs[i] != labs[i - 1]);
    }

    // ---- t = 0 init ----
    float a = NEGF;
    if (s == 0) a = __logf(rowring[0][Cn - 1] + EPSF);
    else if (s == 1) a = __logf(rowring[0][myext] + EPSF);
    if (s >= 0) abuf[0][2 + s] = a;

    if (tid >= 128 && tid < 160) {        // stage A for row 0
        const float4* r4 = (const float4*)rowring[0];
        float4 x = r4[(tid - 128) * 2], y = r4[(tid - 128) * 2 + 1];
        partA[0][tid - 128] = ((x.x + x.y) + (x.z + x.w)) + ((y.x + y.y) + (y.z + y.w));
    }
    __syncthreads();

    // ---- main recurrence over t = 1..T-1 ----
    int pb = 0;
    for (int t = 1; t < Tn; ++t) {
        const int slot = t % DEPTH;

        // prefetch row t+DEPTH-1 into slot (t-1)%DEPTH (freed last iter)
        if (tid < 64) {
            const int rt = t + DEPTH - 1;
            const int ps = (t - 1) % DEPTH;
            if (rt < Tn) {
                unsigned saddr = (unsigned)__cvta_generic_to_shared(&rowring[ps][tid * 4]);
                const float* g = rowbase + (size_t)rt * Cn + tid * 4;
                asm volatile("cp.async.cg.shared.global [%0], [%1], 16;\n" :: "r"(saddr), "l"(g));
            }
            asm volatile("cp.async.commit_group;\n");
        }

        float anew = NEGF;
        if (s >= 0) {
            const float gv = rowring[slot][myext] + EPSF;
            const float a1 = a;
            const float a2 = abuf[pb][1 + s];            // alpha[s-1]
            if (oddst) {
                const float a3 = skipok ? abuf[pb][s] : NEGF;  // alpha[s-2]
                const float mx2 = fmaxf(a1, a2), mn2 = fminf(a1, a2);
                const float m   = fmaxf(mx2, a3);
                const float mid = fminf(mx2, fmaxf(mn2, a3));
                const float lo  = fminf(mn2, a3);
                const float sum = 1.0f + __expf(mid - m) + __expf(lo - m);
                anew = m + __logf(sum * gv);
            } else {
                const float m  = fmaxf(a1, a2);
                const float mn = fminf(a1, a2);
                const float sum = 1.0f + __expf(mn - m);
                anew = m + __logf(sum * gv);
            }
        }

        // stage A: partial row sums for row t (off the recurrence chain)
        if (tid >= 128 && tid < 160) {
            const float4* r4 = (const float4*)rowring[slot];
            float4 x = r4[(tid - 128) * 2], y = r4[(tid - 128) * 2 + 1];
            partA[t & 1][tid - 128] =
                ((x.x + x.y) + (x.z + x.w)) + ((y.x + y.y) + (y.z + y.w));
        }
        // stage B: finalize row t-1 (rotating single thread)
        if (tid == 132 + ((t - 1) & 7)) {
            const float4* p4 = (const float4*)partA[(t - 1) & 1];
            float tot = 0.f;
            #pragma unroll
            for (int j = 0; j < 8; ++j) { float4 v = p4[j]; tot += ((v.x + v.y) + (v.z + v.w)); }
            sums[t - 1] = tot + (float)Cn * EPSF;
        }

        if (s >= 0) { abuf[pb ^ 1][2 + s] = anew; a = anew; }

        asm volatile("cp.async.wait_group %0;\n" :: "n"(DEPTH - 1));
        __syncthreads();
        pb ^= 1;
    }

    // ---- finalize: stage B for row T-1, then D = sum_t log(rowsum_t), then loss ----
    if (tid == 0) {
        const float4* p4 = (const float4*)partA[(Tn - 1) & 1];
        float tot = 0.f;
        #pragma unroll
        for (int j = 0; j < 8; ++j) { float4 v = p4[j]; tot += ((v.x + v.y) + (v.z + v.w)); }
        sums[Tn - 1] = tot + (float)Cn * EPSF;
    }
    __syncthreads();

    float l = 0.f;
    if (tid < 256) {
        #pragma unroll
        for (int j = 0; j < 4; ++j) l += __logf(sums[tid + 256 * j]);
        #pragma unroll
        for (int o = 16; o > 0; o >>= 1) l += __shfl_xor_sync(0xffffffffu, l, o);
        if ((tid & 31) == 0) wsum[tid >> 5] = l;
    }
    __syncthreads();

    if (tid == 0) {
        float Dv = 0.f;
        #pragma unroll
        for (int j = 0; j < 8; ++j) Dv += wsum[j];
        // alpha(T-1) lives in abuf[pb] (pb flipped T-1 times)
        const float x = abuf[pb][2 + (Sn - 2)];   // s = 255
        const float y = abuf[pb][2 + (Sn - 1)];   // s = 256
        const float m = fmaxf(x, y);
        const float lse = m + __logf(__expf(x - m) + __expf(y - m));
        out[b] = Dv - lse;                        // loss = D - LSE(alpha_tilde)
    }
}

extern "C" void kernel_launch(void* const* d_in, const int* in_sizes, int n_in,
                              void* d_out, int out_size)
{
    // identify inputs by element count: y_true = B*L, y_pred = B*T*C
    int iy = (in_sizes[0] == Bn * Ln) ? 0 : 1;
    const void*  yt = d_in[iy];
    const float* yp = (const float*)d_in[1 - iy];
    ctc_kernel<<<Bn, NTHREADS>>>(yt, yp, (float*)d_out);
}

// round 3
// speedup vs baseline: 1.7724x; 1.7724x over previous
#include <cuda_runtime.h>
#include <cstdint>

#define Bn 256
#define Tn 1024
#define Cn 256
#define Ln 128
#define NPER 512          // 512 periods x 2 steps, t = 2p+1, 2p+2 (last guarded)
#define RING 12
#define NEGF (-1e30f)
#define EPSF (1e-7f)
#define NTH 256           // 8 warps

// Roles:
//   tid   0..128 : recurrence, thread k owns states 2k, 2k+1 (W=2, K=2 halo scheme)
//   tid 160..223 : cp.async loaders (64 threads x 16B = 1KB row)
//   tid 224..255 : per-row softmax-denominator sums

__device__ __forceinline__ float upd2(float a1, float a2, float v) {
    const float m  = fmaxf(a1, a2);
    const float mn = fminf(a1, a2);
    return m + __logf((1.0f + __expf(mn - m)) * v);
}
__device__ __forceinline__ float upd3(float a1, float a2, float a3, float v) {
    const float mx2 = fmaxf(a1, a2), mn2 = fminf(a1, a2);
    const float m   = fmaxf(mx2, a3);
    const float mid = fminf(mx2, fmaxf(mn2, a3));
    const float lo  = fminf(mn2, a3);
    return m + __logf((1.0f + __expf(mid - m) + __expf(lo - m)) * v);
}

__global__ __launch_bounds__(NTH, 2)
void ctc_kernel(const void* __restrict__ yt_raw,
                const float* __restrict__ yp,
                float* __restrict__ out)
{
    __shared__ __align__(16) float ring[RING][Cn];   // 12KB row ring
    __shared__ __align__(16) float abuf[2][264];     // state s at [4+s]; [0..3] = NEG pad
    __shared__ float sums[Tn];
    __shared__ int   labs[132];                      // labels + blank pad
    __shared__ float wred[8];
    __shared__ int   flag64;

    const int b   = blockIdx.x;
    const int tid = threadIdx.x;
    const float* rowbase = yp + (size_t)b * Tn * Cn;

    if (tid == 0) flag64 = 1;

    // prologue: rows 0..9
    if (tid >= 160 && tid < 224) {
        const int lt = tid - 160;
        #pragma unroll
        for (int r = 0; r < 10; ++r) {
            unsigned sa = (unsigned)__cvta_generic_to_shared(&ring[r][lt * 4]);
            const float* g = rowbase + (size_t)r * Cn + lt * 4;
            asm volatile("cp.async.cg.shared.global [%0], [%1], 16;\n" :: "r"(sa), "l"(g));
        }
        asm volatile("cp.async.commit_group;\n");
    }
    __syncthreads();

    // label dtype detect (int64 -> odd int32 words of first 128 pairs are 0)
    if (tid < 128) { if (((const int*)yt_raw)[2 * tid + 1] != 0) flag64 = 0; }
    __syncthreads();

    if (tid < Ln) {
        labs[tid] = flag64 ? (int)((const long long*)yt_raw)[(size_t)b * Ln + tid]
                           : ((const int*)yt_raw)[(size_t)b * Ln + tid];
    }
    if (tid >= Ln && tid < 132) labs[tid] = Cn - 1;
    if (tid >= 132 && tid < 136) { abuf[0][tid - 132] = NEGF; abuf[1][tid - 132] = NEGF; }
    if (tid >= 160 && tid < 224) asm volatile("cp.async.wait_group 0;\n");
    __syncthreads();

    // per-thread metadata: window idx 0..5 -> state s = 2k-4+idx; only idx 3,5 are label states
    int vo3 = Cn - 1, vo5 = Cn - 1;
    float sk3 = 0.f, sk5 = 0.f;
    const int k = tid;
    if (tid < 129) {
        if (k >= 1) {
            vo3 = labs[k - 1];
            if (k >= 2 && labs[k - 1] != labs[k - 2]) sk3 = 1.f;
        }
        vo5 = labs[k];                     // k=128 -> pad (junk state 257)
        if (k >= 1 && labs[k] != labs[k - 1]) sk5 = 1.f;
    }

    // t = 0 init
    if (tid < 129) {
        float a0 = NEGF, a1 = NEGF;
        if (k == 0) {
            a0 = __logf(ring[0][Cn - 1] + EPSF);
            a1 = __logf(ring[0][labs[0]] + EPSF);
        }
        float2 w = { a0, a1 };
        *(float2*)&abuf[0][4 + 2 * k] = w;
    }
    if (tid >= 224) {                      // row-0 denominator
        const int l = tid - 224;
        const float4* r4 = (const float4*)ring[0];
        float4 x = r4[l], y = r4[l + 32];
        float part = ((x.x + x.y) + (x.z + x.w)) + ((y.x + y.y) + (y.z + y.w));
        #pragma unroll
        for (int o = 16; o; o >>= 1) part += __shfl_xor_sync(0xffffffffu, part, o);
        if (l == 0) sums[0] = part + (float)Cn * EPSF;
    }
    __syncthreads();

    // ---- main loop: 512 periods x 2 steps ----
    int cur = 0;
    int s0 = 1;                            // slot of row (2p+1): (2p+1) % 12
    for (int p = 0; p < NPER; ++p) {
        const int s1 = (s0 + 1 < RING) ? s0 + 1 : 0;

        if (tid < 129) {
            const float2 h0 = *(const float2*)&abuf[cur][2 * k];
            const float2 h1 = *(const float2*)&abuf[cur][2 * k + 2];
            const float2 h2 = *(const float2*)&abuf[cur][2 * k + 4];
            float A0 = h0.x, A1 = h0.y, A2 = h1.x, A3 = h1.y, A4 = h2.x, A5 = h2.y;

            const float* r0 = ring[s0];
            // step jj=0 (t = 2p+1, always < Tn): update idx 5..2 with OLD values
            {
                const float v2 = r0[Cn - 1] + EPSF;
                const float v3 = r0[vo3] + EPSF;
                const float v4 = r0[Cn - 1] + EPSF;
                const float v5 = r0[vo5] + EPSF;
                const float a3_5 = sk5 > 0.f ? A3 : NEGF;
                const float a3_3 = sk3 > 0.f ? A1 : NEGF;
                const float n5 = upd3(A5, A4, a3_5, v5);
                const float n4 = upd2(A4, A3, v4);
                const float n3 = upd3(A3, A2, a3_3, v3);
                const float n2 = upd2(A2, A1, v2);
                A5 = n5; A4 = n4; A3 = n3; A2 = n2;
            }
            // step jj=1 (t = 2p+2): update idx 5,4
            if (p < NPER - 1) {
                const float* r1 = ring[s1];
                const float v4 = r1[Cn - 1] + EPSF;
                const float v5 = r1[vo5] + EPSF;
                const float a3_5 = sk5 > 0.f ? A3 : NEGF;
                const float n5 = upd3(A5, A4, a3_5, v5);
                const float n4 = upd2(A4, A3, v4);
                A5 = n5; A4 = n4;
            }
            float2 w = { A4, A5 };
            *(float2*)&abuf[cur ^ 1][4 + 2 * k] = w;
        }
        else if (tid >= 160 && tid < 224) {            // loaders: rows 2p+10, 2p+11
            const int lt = tid - 160;
            #pragma unroll
            for (int rr = 0; rr < 2; ++rr) {
                const int rt = 2 * p + 10 + rr;
                if (rt < Tn) {
                    int sl = rt % RING;
                    unsigned sa = (unsigned)__cvta_generic_to_shared(&ring[sl][lt * 4]);
                    const float* g = rowbase + (size_t)rt * Cn + lt * 4;
                    asm volatile("cp.async.cg.shared.global [%0], [%1], 16;\n" :: "r"(sa), "l"(g));
                }
            }
            asm volatile("cp.async.commit_group;\n");
            asm volatile("cp.async.wait_group 2;\n");
        }
        else if (tid >= 224) {                          // row sums for t = 2p+1, 2p+2
            const int l = tid - 224;
            const float4* ra = (const float4*)ring[s0];
            float4 xa = ra[l], ya = ra[l + 32];
            float pa = ((xa.x + xa.y) + (xa.z + xa.w)) + ((ya.x + ya.y) + (ya.z + ya.w));
            float pb = 0.f;
            if (p < NPER - 1) {
                const float4* rb = (const float4*)ring[s1];
                float4 xb = rb[l], yb = rb[l + 32];
                pb = ((xb.x + xb.y) + (xb.z + xb.w)) + ((yb.x + yb.y) + (yb.z + yb.w));
            }
            #pragma unroll
            for (int o = 16; o; o >>= 1) {
                pa += __shfl_xor_sync(0xffffffffu, pa, o);
                pb += __shfl_xor_sync(0xffffffffu, pb, o);
            }
            if (l == 0) {
                sums[2 * p + 1] = pa + (float)Cn * EPSF;
                if (p < NPER - 1) sums[2 * p + 2] = pb + (float)Cn * EPSF;
            }
        }
        __syncthreads();
        cur ^= 1;
        s0 += 2; if (s0 >= RING) s0 -= RING;
    }

    // ---- epilogue: D = sum_t log(rowsum_t); loss = D - LSE(alpha[S-2], alpha[S-1]) ----
    float acc = 0.f;
    #pragma unroll
    for (int j = 0; j < Tn / NTH; ++j) acc += __logf(sums[tid + NTH * j]);
    #pragma unroll
    for (int o = 16; o; o >>= 1) acc += __shfl_xor_sync(0xffffffffu, acc, o);
    if ((tid & 31) == 0) wred[tid >> 5] = acc;
    __syncthreads();

    if (tid == 0) {
        float D = 0.f;
        #pragma unroll
        for (int w = 0; w < 8; ++w) D += wred[w];
        const float x = abuf[cur][4 + 255];    // s = S-2
        const float y = abuf[cur][4 + 256];    // s = S-1
        const float m = fmaxf(x, y);
        out[b] = D - (m + __logf(__expf(x - m) + __expf(y - m)));
    }
}

extern "C" void kernel_launch(void* const* d_in, const int* in_sizes, int n_in,
                              void* d_out, int out_size)
{
    int iy = (in_sizes[0] == Bn * Ln) ? 0 : 1;
    const void*  yt = d_in[iy];
    const float* yp = (const float*)d_in[1 - iy];
    ctc_kernel<<<Bn, NTH>>>(yt, yp, (float*)d_out);
}

// round 4
// speedup vs baseline: 2.0705x; 1.1682x over previous
#include <cuda_runtime.h>
#include <cstdint>

#define Bn 256
#define Tn 1024
#define Cn 256
#define Ln 128
#define NPER 512          // 512 periods x 2 steps, t = 2p+1, 2p+2 (last guarded)
#define RING 12
#define NEGF (-1e30f)
#define EPSF (1e-7f)
#define NTH 224           // 7 warps
#define LN2F 0.6931471805599453f

// Roles (one rec warp per SMSP):
//   tid   0..127 : recurrence warps 0-3; thread k owns states 2k, 2k+1 (W=2, K=2)
//   tid 128..159 : warp 4: per-row denominator sums + blank-emission history
//   tid 160..223 : warps 5,6: cp.async loaders (64 x 16B = 1KB row)
// State 256 is excluded from the recurrence (nothing depends on it) and is
// reconstructed in the epilogue from the A255 + blank-emission histories.

__device__ __forceinline__ float ex2f(float x){ float r; asm("ex2.approx.ftz.f32 %0, %1;" : "=f"(r) : "f"(x)); return r; }
__device__ __forceinline__ float lg2f(float x){ float r; asm("lg2.approx.ftz.f32 %0, %1;" : "=f"(r) : "f"(x)); return r; }

// log2-domain LSE updates with emission folded in: m + lg2((1+sum)*v)
__device__ __forceinline__ float upd2(float a1, float a2, float v) {
    const float m = fmaxf(a1, a2);
    const float d = fminf(a1, a2) - m;
    return m + lg2f(fmaf(ex2f(d), v, v));
}
__device__ __forceinline__ float upd3(float a1, float a2, float a3, float v) {
    const float mx2 = fmaxf(a1, a2), mn2 = fminf(a1, a2);
    const float m   = fmaxf(mx2, a3);
    const float mid = fminf(mx2, fmaxf(mn2, a3));
    const float lo  = fminf(mn2, a3);
    const float s   = ex2f(mid - m) + ex2f(lo - m);
    return m + lg2f(fmaf(s, v, v));
}

__global__ __launch_bounds__(NTH, 2)
void ctc_kernel(const void* __restrict__ yt_raw,
                const float* __restrict__ yp,
                float* __restrict__ out)
{
    __shared__ __align__(16) float ring[RING][Cn];   // 12KB row ring
    __shared__ __align__(16) float abuf[2][264];     // state s at [4+s]; [0..3] NEG pad
    __shared__ float sums[Tn];                       // per-row sum(p) + C*eps (linear)
    __shared__ float hist[Tn];                       // A255(t) history (base-2)
    __shared__ float vbh[Tn];                        // blank emission row[t][255] (raw)
    __shared__ float pre[Tn];                        // within-chunk prefix of lg2(vb+eps)
    __shared__ float csum[128], coff[128];
    __shared__ int   labs[132];
    __shared__ float wredA[8], wredB[8], wredC[8];
    __shared__ float PtotS;
    __shared__ int   flag64;

    const int b   = blockIdx.x;
    const int tid = threadIdx.x;
    const float* rowbase = yp + (size_t)b * Tn * Cn;

    if (tid == 0) flag64 = 1;

    // prologue: rows 0..9
    if (tid >= 160) {
        const int lt = tid - 160;
        #pragma unroll
        for (int r = 0; r < 10; ++r) {
            unsigned sa = (unsigned)__cvta_generic_to_shared(&ring[r][lt * 4]);
            const float* g = rowbase + (size_t)r * Cn + lt * 4;
            asm volatile("cp.async.cg.shared.global [%0], [%1], 16;\n" :: "r"(sa), "l"(g));
        }
        asm volatile("cp.async.commit_group;\n");
    }
    __syncthreads();

    // label dtype detect (int64 -> odd int32 words of first 128 pairs are 0)
    if (tid < 128) { if (((const int*)yt_raw)[2 * tid + 1] != 0) flag64 = 0; }
    __syncthreads();

    if (tid < Ln) {
        labs[tid] = flag64 ? (int)((const long long*)yt_raw)[(size_t)b * Ln + tid]
                           : ((const int*)yt_raw)[(size_t)b * Ln + tid];
    }
    if (tid >= Ln && tid < 132) labs[tid] = Cn - 1;
    if (tid >= 132 && tid < 136) { abuf[0][tid - 132] = NEGF; abuf[1][tid - 132] = NEGF; }
    if (tid == 136) hist[0] = NEGF;       // A255 at t=0
    if (tid >= 160) asm volatile("cp.async.wait_group 0;\n");
    __syncthreads();

    // per-thread metadata: window idx 0..5 -> state s = 2k-4+idx; idx 3,5 are labels
    const int k = tid;
    int vo3 = Cn - 1, vo5 = Cn - 1;
    bool sk3 = false, sk5 = false;
    if (tid < 128) {
        if (k >= 1) {
            vo3 = labs[k - 1];
            sk3 = (k >= 2) && (labs[k - 1] != labs[k - 2]);
        }
        vo5 = labs[k];
        sk5 = (k >= 1) && (labs[k] != labs[k - 1]);
    }

    // t = 0 init (base-2)
    if (tid < 128) {
        float a0 = NEGF, a1 = NEGF;
        if (k == 0) {
            a0 = lg2f(ring[0][Cn - 1] + EPSF);
            a1 = lg2f(ring[0][labs[0]] + EPSF);
        }
        float2 w = { a0, a1 };
        *(float2*)&abuf[0][4 + 2 * k] = w;
    }
    if (tid >= 128 && tid < 160) {        // row-0 denominator
        const int l = tid - 128;
        const float4* r4 = (const float4*)ring[0];
        float4 x = r4[l], y = r4[l + 32];
        float part = ((x.x + x.y) + (x.z + x.w)) + ((y.x + y.y) + (y.z + y.w));
        #pragma unroll
        for (int o = 16; o; o >>= 1) part += __shfl_xor_sync(0xffffffffu, part, o);
        if (l == 0) sums[0] = part + (float)Cn * EPSF;
    }
    __syncthreads();

    // ---- main loop: 512 periods x 2 steps ----
    int cur = 0;
    int s0 = 1;                            // slot of row (2p+1)
    for (int p = 0; p < NPER; ++p) {
        const int s1 = (s0 + 1 < RING) ? s0 + 1 : 0;

        if (tid < 128) {
            const float2 h0 = *(const float2*)&abuf[cur][2 * k];
            const float2 h1 = *(const float2*)&abuf[cur][2 * k + 2];
            const float2 h2 = *(const float2*)&abuf[cur][2 * k + 4];
            float A1 = h0.y, A2 = h1.x, A3 = h1.y, A4 = h2.x, A5 = h2.y;

            const float* r0 = ring[s0];
            // step 0 (t = 2p+1)
            {
                const float vb = r0[Cn - 1] + EPSF;
                const float v3 = r0[vo3] + EPSF;
                const float v5 = r0[vo5] + EPSF;
                const float n5 = upd3(A5, A4, sk5 ? A3 : NEGF, v5);
                const float n4 = upd2(A4, A3, vb);
                const float n3 = upd3(A3, A2, sk3 ? A1 : NEGF, v3);
                const float n2 = upd2(A2, A1, vb);
                A5 = n5; A4 = n4; A3 = n3; A2 = n2;
            }
            if (k == 127) hist[2 * p + 1] = A5;         // A255 history
            // step 1 (t = 2p+2)
            if (p < NPER - 1) {
                const float* r1 = ring[s1];
                const float vb = r1[Cn - 1] + EPSF;
                const float v5 = r1[vo5] + EPSF;
                const float n5 = upd3(A5, A4, sk5 ? A3 : NEGF, v5);
                const float n4 = upd2(A4, A3, vb);
                A5 = n5; A4 = n4;
                if (k == 127) hist[2 * p + 2] = A5;
            }
            float2 w = { A4, A5 };
            *(float2*)&abuf[cur ^ 1][4 + 2 * k] = w;
        }
        else if (tid < 160) {                           // sums + blank-emission capture
            const int l = tid - 128;
            const float4* ra = (const float4*)ring[s0];
            float4 xa = ra[l], ya = ra[l + 32];
            float pa = ((xa.x + xa.y) + (xa.z + xa.w)) + ((ya.x + ya.y) + (ya.z + ya.w));
            float pb = 0.f; float4 yb2 = {0.f,0.f,0.f,0.f};
            if (p < NPER - 1) {
                const float4* rb = (const float4*)ring[s1];
                float4 xb = rb[l], yb = rb[l + 32]; yb2 = yb;
                pb = ((xb.x + xb.y) + (xb.z + xb.w)) + ((yb.x + yb.y) + (yb.z + yb.w));
            }
            if (l == 31) {                 // ya.w / yb2.w = row[255]
                vbh[2 * p + 1] = ya.w;
                if (p < NPER - 1) vbh[2 * p + 2] = yb2.w;
            }
            #pragma unroll
            for (int o = 16; o; o >>= 1) {
                pa += __shfl_xor_sync(0xffffffffu, pa, o);
                pb += __shfl_xor_sync(0xffffffffu, pb, o);
            }
            if (l == 0) {
                sums[2 * p + 1] = pa + (float)Cn * EPSF;
                if (p < NPER - 1) sums[2 * p + 2] = pb + (float)Cn * EPSF;
            }
        }
        else {                                          // loaders: rows 2p+10, 2p+11
            const int lt = tid - 160;
            #pragma unroll
            for (int rr = 0; rr < 2; ++rr) {
                const int rt = 2 * p + 10 + rr;
                if (rt < Tn) {
                    int sl = rt % RING;
                    unsigned sa = (unsigned)__cvta_generic_to_shared(&ring[sl][lt * 4]);
                    const float* g = rowbase + (size_t)rt * Cn + lt * 4;
                    asm volatile("cp.async.cg.shared.global [%0], [%1], 16;\n" :: "r"(sa), "l"(g));
                }
            }
            asm volatile("cp.async.commit_group;\n");
            asm volatile("cp.async.wait_group 2;\n");
        }
        __syncthreads();
        cur ^= 1;
        s0 += 2; if (s0 >= RING) s0 -= RING;
    }

    // ==== epilogue ====
    // Stage A: chunked prefix sums of lgb[u] = lg2(vbh[u]+eps), u=1..1023 (lgb[0]=0)
    if (tid < 128) {
        const int base = 8 * tid;
        float r = 0.f;
        #pragma unroll
        for (int j = 0; j < 8; ++j) {
            const int u = base + j;
            float x = (u == 0) ? 0.f : lg2f(vbh[u] + EPSF);
            r += x;
            pre[u] = r;
        }
        csum[tid] = r;
    }
    __syncthreads();

    // Stage B: exclusive scan of 128 chunk sums (one warp)
    if (tid < 32) {
        float c0 = csum[4*tid], c1 = csum[4*tid+1], c2 = csum[4*tid+2], c3 = csum[4*tid+3];
        float tot = ((c0 + c1) + (c2 + c3));
        float sc = tot;
        #pragma unroll
        for (int o = 1; o < 32; o <<= 1) {
            float v = __shfl_up_sync(0xffffffffu, sc, o);
            if (tid >= o) sc += v;
        }
        const float ex = sc - tot;         // exclusive prefix
        coff[4*tid]   = ex;
        coff[4*tid+1] = ex + c0;
        coff[4*tid+2] = ex + c0 + c1;
        coff[4*tid+3] = ex + c0 + c1 + c2;
        if (tid == 31) PtotS = sc;         // P(1023)
    }
    __syncthreads();

    // Stage C pass 1: term(u) = hist[u] + (Ptot - P(u)), max-reduce; also D2 partial
    const float Ptot = PtotS;
    float lm = -3.0e38f;
    for (int u = tid; u < Tn - 1; u += NTH) {
        const float term = hist[u] + (Ptot - (coff[u >> 3] + pre[u]));
        lm = fmaxf(lm, term);
    }
    float d2 = 0.f;
    for (int t2 = tid; t2 < Tn; t2 += NTH) d2 += lg2f(sums[t2]);
    #pragma unroll
    for (int o = 16; o; o >>= 1) {
        lm = fmaxf(lm, __shfl_xor_sync(0xffffffffu, lm, o));
        d2 += __shfl_xor_sync(0xffffffffu, d2, o);
    }
    if ((tid & 31) == 0) { wredA[tid >> 5] = lm; wredB[tid >> 5] = d2; }
    __syncthreads();

    float M = wredA[0];
    #pragma unroll
    for (int w = 1; w < 7; ++w) M = fmaxf(M, wredA[w]);

    // pass 2: sum of 2^(term - M)
    float se = 0.f;
    for (int u = tid; u < Tn - 1; u += NTH) {
        const float term = hist[u] + (Ptot - (coff[u >> 3] + pre[u]));
        se += ex2f(term - M);
    }
    #pragma unroll
    for (int o = 16; o; o >>= 1) se += __shfl_xor_sync(0xffffffffu, se, o);
    if ((tid & 31) == 0) wredC[tid >> 5] = se;
    __syncthreads();

    if (tid == 0) {
        float S = 0.f, D2 = 0.f;
        #pragma unroll
        for (int w = 0; w < 7; ++w) { S += wredC[w]; D2 += wredB[w]; }
        const float a256 = M + lg2f(S);                 // A256(T-1), base-2
        const float x = abuf[cur][4 + 255];             // A255(T-1), base-2
        const float m2 = fmaxf(x, a256);
        const float lse2 = m2 + lg2f(ex2f(x - m2) + ex2f(a256 - m2));
        out[b] = LN2F * (D2 - lse2);
    }
}

extern "C" void kernel_launch(void* const* d_in, const int* in_sizes, int n_in,
                              void* d_out, int out_size)
{
    int iy = (in_sizes[0] == Bn * Ln) ? 0 : 1;
    const void*  yt = d_in[iy];
    const float* yp = (const float*)d_in[1 - iy];
    ctc_kernel<<<Bn, NTH>>>(yt, yp, (float*)d_out);
}

// round 5
// speedup vs baseline: 2.7347x; 1.3208x over previous
#include <cuda_runtime.h>
#include <cstdint>

#define Bn 256
#define Tn 1024
#define Cn 256
#define Ln 128
#define NPER 256          // 256 periods x 4 steps: t = 4p+1 .. 4p+4 (last guarded)
#define RING 12
#define NEGF (-1e30f)
#define EPSF (1e-7f)
#define NTH 224           // 7 warps
#define LN2F 0.6931471805599453f

// Roles (one rec warp per SMSP):
//   tid   0..127 : recurrence; thread k owns states 2k,2k+1; K=4 steps/barrier with
//                  9-state halo; linear fp32 inside the period, log2 between periods.
//   tid 128..159 : per-row denominator sums + blank-emission capture
//   tid 160..223 : cp.async loaders (64 x 16B = 1KB row), 4 rows/period
// State 256 excluded from recurrence; reconstructed in epilogue from A255 +
// blank-emission histories (validated in R4).

__device__ __forceinline__ float ex2f(float x){ float r; asm("ex2.approx.ftz.f32 %0, %1;" : "=f"(r) : "f"(x)); return r; }
__device__ __forceinline__ float lg2f(float x){ float r; asm("lg2.approx.ftz.f32 %0, %1;" : "=f"(r) : "f"(x)); return r; }

__global__ __launch_bounds__(NTH, 2)
void ctc_kernel(const void* __restrict__ yt_raw,
                const float* __restrict__ yp,
                float* __restrict__ out)
{
    __shared__ __align__(16) float ring[RING][Cn];   // 12KB row ring
    __shared__ __align__(8)  float abuf[2][264];     // log2 alpha, state s at [8+s]; [0..7] NEG pad
    __shared__ float sums[Tn];                       // per-row sum(p)+C*eps
    __shared__ float vbh[Tn];                        // row[t][255] raw
    __shared__ float histL[Tn];                      // A255(t) linear-in-period
    __shared__ float histM[NPER];                    // per-period shift of thread 127
    __shared__ float pre[Tn];
    __shared__ float csum[128], coff[128];
    __shared__ int   labs[132];
    __shared__ float wredA[8], wredB[8], wredC[8];
    __shared__ float PtotS;
    __shared__ int   flag64;

    const int b   = blockIdx.x;
    const int tid = threadIdx.x;
    const float* rowbase = yp + (size_t)b * Tn * Cn;

    if (tid == 0) flag64 = 1;

    // prologue: rows 0..8
    if (tid >= 160) {
        const int lt = tid - 160;
        #pragma unroll
        for (int r = 0; r < 9; ++r) {
            unsigned sa = (unsigned)__cvta_generic_to_shared(&ring[r][lt * 4]);
            const float* g = rowbase + (size_t)r * Cn + lt * 4;
            asm volatile("cp.async.cg.shared.global [%0], [%1], 16;\n" :: "r"(sa), "l"(g));
        }
        asm volatile("cp.async.commit_group;\n");
    }
    __syncthreads();

    if (tid < 128) { if (((const int*)yt_raw)[2 * tid + 1] != 0) flag64 = 0; }
    __syncthreads();

    if (tid < Ln) {
        labs[tid] = flag64 ? (int)((const long long*)yt_raw)[(size_t)b * Ln + tid]
                           : ((const int*)yt_raw)[(size_t)b * Ln + tid];
    }
    if (tid >= Ln && tid < 132) labs[tid] = Cn - 1;
    if (tid >= 132 && tid < 140) { abuf[0][tid - 132] = NEGF; abuf[1][tid - 132] = NEGF; }
    if (tid >= 160) asm volatile("cp.async.wait_group 0;\n");
    __syncthreads();

    // metadata: window idx 0..9 -> state s = 2k-8+idx; odd idx 3,5,7,9 are labels i=k-3..k
    const int k = tid;
    int vo9 = Cn-1, vo7 = Cn-1, vo5 = Cn-1, vo3 = Cn-1;
    float sk9 = 0.f, sk7 = 0.f, sk5 = 0.f, sk3 = 0.f;
    if (tid < 128) {
        vo9 = labs[k];
        if (k >= 1 && labs[k] != labs[k-1]) sk9 = 1.f;
        if (k >= 1) { vo7 = labs[k-1]; if (k >= 2 && labs[k-1] != labs[k-2]) sk7 = 1.f; }
        if (k >= 2) { vo5 = labs[k-2]; if (k >= 3 && labs[k-2] != labs[k-3]) sk5 = 1.f; }
        if (k >= 3) { vo3 = labs[k-3]; if (k >= 4 && labs[k-3] != labs[k-4]) sk3 = 1.f; }
    }

    // t = 0 init (log2 domain)
    if (tid < 128) {
        float a0 = NEGF, a1 = NEGF;
        if (k == 0) {
            a0 = lg2f(ring[0][Cn - 1] + EPSF);
            a1 = lg2f(ring[0][labs[0]] + EPSF);
        }
        float2 w = { a0, a1 };
        *(float2*)&abuf[0][8 + 2 * k] = w;
    }
    if (tid >= 128 && tid < 160) {
        const int l = tid - 128;
        const float4* r4 = (const float4*)ring[0];
        float4 x = r4[l], y = r4[l + 32];
        float part = ((x.x + x.y) + (x.z + x.w)) + ((y.x + y.y) + (y.z + y.w));
        #pragma unroll
        for (int o = 16; o; o >>= 1) part += __shfl_xor_sync(0xffffffffu, part, o);
        if (l == 0) sums[0] = part + (float)Cn * EPSF;
    }
    __syncthreads();

    // ---- main loop: 256 periods x 4 steps ----
    int cur = 0;
    int s0 = 1;                            // (4p+1) % 12
    for (int p = 0; p < NPER; ++p) {
        if (tid < 128) {
            const float2* hp = (const float2*)&abuf[cur][2 * k];  // states 2k-8 .. 2k+1
            float2 h0 = hp[0], h1 = hp[1], h2 = hp[2], h3 = hp[3], h4 = hp[4];
            float A1 = h0.y, A2 = h1.x, A3 = h1.y, A4 = h2.x, A5 = h2.y,
                  A6 = h3.x, A7 = h3.y, A8 = h4.x, A9 = h4.y;
            const float m = fmaxf(fmaxf(fmaxf(A1, A2), fmaxf(A3, A4)),
                                  fmaxf(fmaxf(A5, A6), fmaxf(A7, fmaxf(A8, A9))));
            A1 = ex2f(A1 - m); A2 = ex2f(A2 - m); A3 = ex2f(A3 - m);
            A4 = ex2f(A4 - m); A5 = ex2f(A5 - m); A6 = ex2f(A6 - m);
            A7 = ex2f(A7 - m); A8 = ex2f(A8 - m); A9 = ex2f(A9 - m);

            #pragma unroll
            for (int jj = 0; jj < 4; ++jj) {
                if (4 * p + 1 + jj < Tn) {
                    int sl = s0 + jj; if (sl >= RING) sl -= RING;
                    const float* r = ring[sl];
                    const float vb = r[Cn - 1] + EPSF;
                    {   // idx 9, 8 every step
                        const float v9 = r[vo9] + EPSF;
                        A9 = fmaf(sk9, A7, A9 + A8) * v9;
                        A8 = (A8 + A7) * vb;
                    }
                    if (jj <= 2) { const float v7 = r[vo7] + EPSF;
                                   A7 = fmaf(sk7, A5, A7 + A6) * v7; A6 = (A6 + A5) * vb; }
                    if (jj <= 1) { const float v5 = r[vo5] + EPSF;
                                   A5 = fmaf(sk5, A3, A5 + A4) * v5; A4 = (A4 + A3) * vb; }
                    if (jj == 0) { const float v3 = r[vo3] + EPSF;
                                   A3 = fmaf(sk3, A1, A3 + A2) * v3; A2 = (A2 + A1) * vb; }
                    if (k == 127) histL[4 * p + 1 + jj] = A9;
                }
            }
            if (k == 127) histM[p] = m;
            const float L8 = fmaxf(m + lg2f(A8), NEGF);
            const float L9 = fmaxf(m + lg2f(A9), NEGF);
            float2 w = { L8, L9 };
            *(float2*)&abuf[cur ^ 1][8 + 2 * k] = w;
        }
        else if (tid < 160) {              // sums + blank-emission capture, 4 rows
            const int l = tid - 128;
            float pr[4];
            #pragma unroll
            for (int rr = 0; rr < 4; ++rr) {
                const int t = 4 * p + 1 + rr;
                if (t < Tn) {
                    int sl = s0 + rr; if (sl >= RING) sl -= RING;
                    const float4* r4 = (const float4*)ring[sl];
                    float4 x = r4[l], y = r4[l + 32];
                    pr[rr] = ((x.x + x.y) + (x.z + x.w)) + ((y.x + y.y) + (y.z + y.w));
                    if (l == 31) vbh[t] = y.w;
                } else pr[rr] = 0.f;
            }
            #pragma unroll
            for (int o = 16; o; o >>= 1) {
                pr[0] += __shfl_xor_sync(0xffffffffu, pr[0], o);
                pr[1] += __shfl_xor_sync(0xffffffffu, pr[1], o);
                pr[2] += __shfl_xor_sync(0xffffffffu, pr[2], o);
                pr[3] += __shfl_xor_sync(0xffffffffu, pr[3], o);
            }
            if (l == 0) {
                #pragma unroll
                for (int rr = 0; rr < 4; ++rr) {
                    const int t = 4 * p + 1 + rr;
                    if (t < Tn) sums[t] = pr[rr] + (float)Cn * EPSF;
                }
            }
        }
        else {                             // loaders: rows 4p+9 .. 4p+12
            const int lt = tid - 160;
            int sw = s0 + 8; if (sw >= RING) sw -= RING;
            #pragma unroll
            for (int rr = 0; rr < 4; ++rr) {
                const int rt = 4 * p + 9 + rr;
                if (rt < Tn) {
                    int sl = sw + rr; if (sl >= RING) sl -= RING;
                    unsigned sa = (unsigned)__cvta_generic_to_shared(&ring[sl][lt * 4]);
                    const float* g = rowbase + (size_t)rt * Cn + lt * 4;
                    asm volatile("cp.async.cg.shared.global [%0], [%1], 16;\n" :: "r"(sa), "l"(g));
                }
            }
            asm volatile("cp.async.commit_group;\n");
            asm volatile("cp.async.wait_group 1;\n");
        }
        __syncthreads();
        cur ^= 1;
        s0 += 4; if (s0 >= RING) s0 -= RING;
    }

    // ==== epilogue (A256 reconstruction + D), validated structure from R4 ====
    // Stage A: chunked prefix of lgb[u] = lg2(vbh[u]+eps), lgb[0] = 0
    if (tid < 128) {
        const int base = 8 * tid;
        float r = 0.f;
        #pragma unroll
        for (int j = 0; j < 8; ++j) {
            const int u = base + j;
            float x = (u == 0) ? 0.f : lg2f(vbh[u] + EPSF);
            r += x;
            pre[u] = r;
        }
        csum[tid] = r;
    }
    __syncthreads();

    if (tid < 32) {                        // exclusive scan of 128 chunk sums
        float c0 = csum[4*tid], c1 = csum[4*tid+1], c2 = csum[4*tid+2], c3 = csum[4*tid+3];
        float tot = ((c0 + c1) + (c2 + c3));
        float sc = tot;
        #pragma unroll
        for (int o = 1; o < 32; o <<= 1) {
            float v = __shfl_up_sync(0xffffffffu, sc, o);
            if (tid >= o) sc += v;
        }
        const float ex = sc - tot;
        coff[4*tid]   = ex;
        coff[4*tid+1] = ex + c0;
        coff[4*tid+2] = ex + c0 + c1;
        coff[4*tid+3] = ex + c0 + c1 + c2;
        if (tid == 31) PtotS = sc;
    }
    __syncthreads();

    const float Ptot = PtotS;
    float lm = -3.0e38f;
    for (int u = tid; u < Tn - 1; u += NTH) {
        const float h = (u == 0) ? NEGF : histM[(u - 1) >> 2] + lg2f(histL[u]);
        lm = fmaxf(lm, h + (Ptot - (coff[u >> 3] + pre[u])));
    }
    float d2 = 0.f;
    for (int t2 = tid; t2 < Tn; t2 += NTH) d2 += lg2f(sums[t2]);
    #pragma unroll
    for (int o = 16; o; o >>= 1) {
        lm = fmaxf(lm, __shfl_xor_sync(0xffffffffu, lm, o));
        d2 += __shfl_xor_sync(0xffffffffu, d2, o);
    }
    if ((tid & 31) == 0) { wredA[tid >> 5] = lm; wredB[tid >> 5] = d2; }
    __syncthreads();

    float M = wredA[0];
    #pragma unroll
    for (int w = 1; w < 7; ++w) M = fmaxf(M, wredA[w]);

    float se = 0.f;
    for (int u = tid; u < Tn - 1; u += NTH) {
        const float h = (u == 0) ? NEGF : histM[(u - 1) >> 2] + lg2f(histL[u]);
        se += ex2f(h + (Ptot - (coff[u >> 3] + pre[u])) - M);
    }
    #pragma unroll
    for (int o = 16; o; o >>= 1) se += __shfl_xor_sync(0xffffffffu, se, o);
    if ((tid & 31) == 0) wredC[tid >> 5] = se;
    __syncthreads();

    if (tid == 0) {
        float S = 0.f, D2 = 0.f;
        #pragma unroll
        for (int w = 0; w < 7; ++w) { S += wredC[w]; D2 += wredB[w]; }
        const float a256 = M + lg2f(S);              // A256(T-1), base-2
        const float x = abuf[cur][8 + 255];          // A255(T-1), base-2
        const float m2 = fmaxf(x, a256);
        const float lse2 = m2 + lg2f(ex2f(x - m2) + ex2f(a256 - m2));
        out[b] = LN2F * (D2 - lse2);
    }
}

extern "C" void kernel_launch(void* const* d_in, const int* in_sizes, int n_in,
                              void* d_out, int out_size)
{
    int iy = (in_sizes[0] == Bn * Ln) ? 0 : 1;
    const void*  yt = d_in[iy];
    const float* yp = (const float*)d_in[1 - iy];
    ctc_kernel<<<Bn, NTH>>>(yt, yp, (float*)d_out);
}